// round 9
// baseline (speedup 1.0000x reference)
#include <cuda_runtime.h>

// GraphPolicyNet: GNN forward pass.
//   - message MLP computed per-NODE (m = lrelu(x @ W_msg)), not per-edge (32x less work)
//   - edges counting-sorted by dst into CSR each launch (int atomics only)
//   - per iteration ONE fused kernel: warp-per-node gather-sum of m rows (L2-resident),
//     update GEMM via shared-mem broadcast, next msg MLP, ping-pong m buffers
//   - global mean folded into last iteration; logits only for 1024 actionable nodes
//   - integer inputs (edge_index, actionable) may arrive as int32 OR int64:
//     detected on-device by sampling odd 32-bit words (int64<2^31 => all zero)
//   - all decoded indices clamped (turns any mis-binding into rel_err, not a fault)

#define N_NODES 100000
#define N_EDGES 3200000
#define EMB 32
#define NFEAT 128
#define NACT 1024
#define SCAN_B 1024
#define NBLK ((N_NODES + SCAN_B - 1) / SCAN_B)   // 98

// ---- scratch (static device memory; no allocation APIs) ----
__device__ float g_x [N_NODES * EMB];
__device__ float g_m0[N_NODES * EMB];
__device__ float g_m1[N_NODES * EMB];
__device__ int   g_src[N_EDGES];
__device__ int   g_dst[N_EDGES];
__device__ int   g_srcSorted[N_EDGES];
__device__ int   g_rowStart[N_NODES + 1];
__device__ int   g_cur[N_NODES];          // histogram counts, then scatter cursors
__device__ int   g_blockSums[NBLK];
__device__ float g_colsum[EMB];
__device__ int   g_ei_is64;
__device__ int   g_act_is64;

__device__ __forceinline__ float lrelu(float z) { return z > 0.f ? z : 0.01f * z; }
__device__ __forceinline__ int clampN(int v) {
    return v < 0 ? 0 : (v >= N_NODES ? N_NODES - 1 : v);
}

// ---- dtype detection: sample odd 32-bit words ----
__global__ void k_detect(const unsigned* __restrict__ ei32,
                         const unsigned* __restrict__ act32) {
    __shared__ int bad_ei, bad_act;
    int t = threadIdx.x;
    if (t == 0) { bad_ei = 0; bad_act = 0; }
    __syncthreads();
    if (t < 32) {
        // 32 odd positions spread across first 3.2M pairs (both layouts have >=6.4M words)
        unsigned pair = (unsigned)((t * 100003u) % 3200000u);
        if (ei32[2u * pair + 1u] != 0u) atomicExch(&bad_ei, 1);
    } else if (t < 64) {
        unsigned i = (unsigned)(t - 32);
        unsigned pair = (i * 13u) % 512u;        // odd word index < 1024 (both layouts ok)
        if (act32[2u * pair + 1u] != 0u) atomicExch(&bad_act, 1);
    }
    __syncthreads();
    if (t == 0) { g_ei_is64 = bad_ei ? 0 : 1; g_act_is64 = bad_act ? 0 : 1; }
}

// ---- init: zero counters & colsum ----
__global__ void k_init() {
    int i = blockIdx.x * blockDim.x + threadIdx.x;
    if (i < N_NODES) g_cur[i] = 0;
    if (i < EMB)     g_colsum[i] = 0.f;
}

// ---- edge decode (int32 or int64) + dst histogram ----
__global__ void k_hist(const void* __restrict__ ei) {
    int e = blockIdx.x * blockDim.x + threadIdx.x;
    if (e >= N_EDGES) return;
    int s, d;
    if (g_ei_is64) {
        const long long* p = (const long long*)ei;
        s = (int)p[e];
        d = (int)p[N_EDGES + e];
    } else {
        const int* p = (const int*)ei;
        s = p[e];
        d = p[N_EDGES + e];
    }
    s = clampN(s); d = clampN(d);
    g_src[e] = s;
    g_dst[e] = d;
    atomicAdd(&g_cur[d], 1);
}

// ---- exclusive scan of counts (2-level) ----
__global__ void k_scan1() {
    __shared__ int sh[SCAN_B];
    int tid = threadIdx.x;
    int i = blockIdx.x * SCAN_B + tid;
    int c = (i < N_NODES) ? g_cur[i] : 0;
    sh[tid] = c;
    __syncthreads();
    for (int off = 1; off < SCAN_B; off <<= 1) {
        int add = (tid >= off) ? sh[tid - off] : 0;
        __syncthreads();
        sh[tid] += add;
        __syncthreads();
    }
    if (i < N_NODES) g_rowStart[i] = sh[tid] - c;   // exclusive within block
    if (tid == SCAN_B - 1) g_blockSums[blockIdx.x] = sh[tid];
}

__global__ void k_scan2() {   // tiny serial scan of 98 block sums
    int run = 0;
    for (int b = 0; b < NBLK; ++b) {
        int t = g_blockSums[b];
        g_blockSums[b] = run;
        run += t;
    }
}

__global__ void k_scan3() {
    int i = blockIdx.x * blockDim.x + threadIdx.x;
    if (i < N_NODES) {
        int v = g_rowStart[i] + g_blockSums[i >> 10];
        g_rowStart[i] = v;
        g_cur[i] = v;                  // scatter cursor
    }
    if (i == 0) g_rowStart[N_NODES] = N_EDGES;
}

// ---- scatter src indices into dst-sorted order ----
__global__ void k_scatter() {
    int e = blockIdx.x * blockDim.x + threadIdx.x;
    if (e >= N_EDGES) return;
    int pos = atomicAdd(&g_cur[g_dst[e]], 1);
    if (pos >= 0 && pos < N_EDGES) g_srcSorted[pos] = g_src[e];
}

// ---- embed: x = lrelu(feats @ W_embed + b), m0 = lrelu(x @ W_msg + b) ----
__global__ void __launch_bounds__(256) k_embed(
    const float* __restrict__ feats, const float* __restrict__ We,
    const float* __restrict__ be,    const float* __restrict__ Wm,
    const float* __restrict__ bm)
{
    __shared__ float sWe[NFEAT * EMB];   // 16 KB
    __shared__ float sWm[EMB * EMB];
    __shared__ float sbe[EMB], sbm[EMB];
    __shared__ float sbuf[8 * NFEAT];
    int tid = threadIdx.x;
    for (int i = tid; i < NFEAT * EMB; i += 256) sWe[i] = We[i];
    for (int i = tid; i < EMB * EMB;   i += 256) sWm[i] = Wm[i];
    if (tid < EMB) { sbe[tid] = be[tid]; sbm[tid] = bm[tid]; }
    __syncthreads();

    int w = tid >> 5, j = tid & 31;
    int node = blockIdx.x * 8 + w;
    if (node >= N_NODES) return;

    #pragma unroll
    for (int k = 0; k < 4; ++k)
        sbuf[w * NFEAT + j + 32 * k] = feats[node * NFEAT + j + 32 * k];
    __syncwarp();

    float a = sbe[j];
    #pragma unroll 16
    for (int k = 0; k < NFEAT; ++k) a += sbuf[w * NFEAT + k] * sWe[k * EMB + j];
    float x = lrelu(a);
    g_x[node * EMB + j] = x;
    __syncwarp();
    sbuf[w * NFEAT + j] = x;
    __syncwarp();

    float mm = sbm[j];
    #pragma unroll
    for (int k = 0; k < EMB; ++k) mm += sbuf[w * NFEAT + k] * sWm[k * EMB + j];
    g_m0[node * EMB + j] = lrelu(mm);
}

// ---- one MP iteration, fused: gather-sum, update GEMM, next msg GEMM ----
__global__ void __launch_bounds__(256) k_iter(
    const float* __restrict__ Wu, const float* __restrict__ bu,
    const float* __restrict__ Wm, const float* __restrict__ bm,
    int parity, int do_colsum)
{
    __shared__ float sWu[64 * EMB];      // 8 KB
    __shared__ float sWm[EMB * EMB];     // 4 KB
    __shared__ float sbu[EMB], sbm[EMB];
    __shared__ float sbuf[8 * 64];
    __shared__ float sred[256];
    int tid = threadIdx.x;
    for (int i = tid; i < 64 * EMB;  i += 256) sWu[i] = Wu[i];
    for (int i = tid; i < EMB * EMB; i += 256) sWm[i] = Wm[i];
    if (tid < EMB) { sbu[tid] = bu[tid]; sbm[tid] = bm[tid]; }
    __syncthreads();

    const float* __restrict__ m_in  = parity ? g_m1 : g_m0;
    float*       __restrict__ m_out = parity ? g_m0 : g_m1;

    int w = tid >> 5, j = tid & 31;
    int node = blockIdx.x * 8 + w;
    float xnew = 0.f;

    if (node < N_NODES) {
        int e   = g_rowStart[node];
        int end = g_rowStart[node + 1];
        float acc = 0.f;
        // 4-way prefetched gather: each warp load is one coalesced 128B row of m
        for (; e + 4 <= end; e += 4) {
            int s0 = g_srcSorted[e + 0];
            int s1 = g_srcSorted[e + 1];
            int s2 = g_srcSorted[e + 2];
            int s3 = g_srcSorted[e + 3];
            float v0 = m_in[s0 * EMB + j];
            float v1 = m_in[s1 * EMB + j];
            float v2 = m_in[s2 * EMB + j];
            float v3 = m_in[s3 * EMB + j];
            acc += v0 + v1 + v2 + v3;
        }
        for (; e < end; ++e) acc += m_in[g_srcSorted[e] * EMB + j];

        float xold = g_x[node * EMB + j];
        sbuf[w * 64 + j]      = xold;
        sbuf[w * 64 + 32 + j] = acc;
        __syncwarp();
        float u = sbu[j];
        #pragma unroll
        for (int k = 0; k < 64; ++k) u += sbuf[w * 64 + k] * sWu[k * EMB + j];
        xnew = lrelu(u);
        g_x[node * EMB + j] = xnew;
        __syncwarp();
        sbuf[w * 64 + j] = xnew;
        __syncwarp();
        float mm = sbm[j];
        #pragma unroll
        for (int k = 0; k < EMB; ++k) mm += sbuf[w * 64 + k] * sWm[k * EMB + j];
        m_out[node * EMB + j] = lrelu(mm);
    }

    if (do_colsum) {     // fold global mean into the last iteration
        sred[tid] = xnew;
        __syncthreads();
        if (tid < 32) {
            float t = 0.f;
            #pragma unroll
            for (int r = 0; r < 8; ++r) t += sred[r * 32 + tid];
            atomicAdd(&g_colsum[tid], t);
        }
    }
}

// ---- head: value + softmax over 1024 actionable logits ----
__global__ void k_final(
    const void* __restrict__ act,
    const float* __restrict__ Wpol, const float* __restrict__ bpol,
    const float* __restrict__ Wval, const float* __restrict__ bval,
    float* __restrict__ out)
{
    __shared__ float sred[NACT];
    __shared__ float sWp[EMB];
    int t = threadIdx.x;
    if (t < EMB) sWp[t] = Wpol[t];
    __syncthreads();

    int node;
    if (g_act_is64) node = (int)((const long long*)act)[t];
    else            node = ((const int*)act)[t];
    node = clampN(node);

    float lg = bpol[0];
    #pragma unroll
    for (int k = 0; k < EMB; ++k) lg += g_x[node * EMB + k] * sWp[k];

    sred[t] = lg;
    __syncthreads();
    for (int off = NACT / 2; off > 0; off >>= 1) {
        if (t < off) sred[t] = fmaxf(sred[t], sred[t + off]);
        __syncthreads();
    }
    float mx = sred[0];
    __syncthreads();
    float ex = expf(lg - mx);
    sred[t] = ex;
    __syncthreads();
    for (int off = NACT / 2; off > 0; off >>= 1) {
        if (t < off) sred[t] += sred[t + off];
        __syncthreads();
    }
    float sm = sred[0];
    out[1 + t] = ex / sm;

    if (t == 0) {
        float v = bval[0];
        #pragma unroll
        for (int k = 0; k < EMB; ++k)
            v += (g_colsum[k] * (1.0f / N_NODES)) * Wval[k];
        out[0] = v;
    }
}

extern "C" void kernel_launch(void* const* d_in, const int* in_sizes, int n_in,
                              void* d_out, int out_size) {
    const float* feats = (const float*)d_in[0];
    const void*  ei    = d_in[1];
    const void*  act   = d_in[2];
    const float* We = (const float*)d_in[3];
    const float* be = (const float*)d_in[4];
    const float* Wm = (const float*)d_in[5];
    const float* bm = (const float*)d_in[6];
    const float* Wu = (const float*)d_in[7];
    const float* bu = (const float*)d_in[8];
    const float* Wv = (const float*)d_in[9];
    const float* bv = (const float*)d_in[10];
    const float* Wp = (const float*)d_in[11];
    const float* bp = (const float*)d_in[12];
    float* out = (float*)d_out;

    int nb_nodes = (N_NODES + 255) / 256;
    int nb_edges = (N_EDGES + 255) / 256;
    int nb_warp8 = (N_NODES + 7) / 8;       // warp-per-node kernels

    // dtype detection + CSR build
    k_detect <<<1, 64>>>((const unsigned*)ei, (const unsigned*)act);
    k_init   <<<nb_nodes, 256>>>();
    k_hist   <<<nb_edges, 256>>>(ei);
    k_scan1  <<<NBLK, SCAN_B>>>();
    k_scan2  <<<1, 1>>>();
    k_scan3  <<<nb_nodes, 256>>>();
    k_scatter<<<nb_edges, 256>>>();

    // GNN
    k_embed<<<nb_warp8, 256>>>(feats, We, be, Wm, bm);
    for (int it = 0; it < 5; ++it)
        k_iter<<<nb_warp8, 256>>>(Wu, bu, Wm, bm, it & 1, it == 4 ? 1 : 0);

    k_final<<<1, NACT>>>(act, Wp, bp, Wv, bv, out);
}

// round 13
// speedup vs baseline: 1.0892x; 1.0892x over previous
#include <cuda_runtime.h>
#include <cuda_fp16.h>

// GraphPolicyNet: GNN forward pass.
//   - message MLP per-NODE (32x less GEMM work than per-edge)
//   - edges counting-sorted by dst into CSR each launch (int atomics only)
//   - per iteration ONE fused kernel: warp-per-node gather-sum of fp16 m rows
//     (half-warp per row, 2 edges per warp-step), update GEMM via smem broadcast,
//     next msg MLP, ping-pong m buffers
//   - global mean folded into last iteration; logits only for 1024 actionable nodes
//   - int inputs may arrive int32 OR int64 (detected on-device); indices clamped

#define N_NODES 100000
#define N_EDGES 3200000
#define EMB 32
#define NFEAT 128
#define NACT 1024
#define SCAN_B 1024
#define NBLK ((N_NODES + SCAN_B - 1) / SCAN_B)   // 98

// ---- scratch (static device memory; no allocation APIs) ----
__device__ float   g_x [N_NODES * EMB];
__device__ __half2 g_m0[N_NODES * (EMB / 2)];    // fp16 messages, 64B/row
__device__ __half2 g_m1[N_NODES * (EMB / 2)];
__device__ int     g_src[N_EDGES];
__device__ int     g_dst[N_EDGES];
__device__ int     g_srcSorted[N_EDGES];
__device__ int     g_rowStart[N_NODES + 1];
__device__ int     g_cur[N_NODES];
__device__ int     g_blockSums[NBLK];
__device__ float   g_colsum[EMB];
__device__ int     g_ei_is64;
__device__ int     g_act_is64;

__device__ __forceinline__ float lrelu(float z) { return z > 0.f ? z : 0.01f * z; }
__device__ __forceinline__ int clampN(int v) {
    return v < 0 ? 0 : (v >= N_NODES ? N_NODES - 1 : v);
}

// ---- dtype detection: sample odd 32-bit words (int64 < 2^31 => all zero) ----
__global__ void k_detect(const unsigned* __restrict__ ei32,
                         const unsigned* __restrict__ act32) {
    __shared__ int bad_ei, bad_act;
    int t = threadIdx.x;
    if (t == 0) { bad_ei = 0; bad_act = 0; }
    __syncthreads();
    if (t < 32) {
        unsigned pair = (unsigned)((t * 100003u) % 3200000u);
        if (ei32[2u * pair + 1u] != 0u) atomicExch(&bad_ei, 1);
    } else if (t < 64) {
        unsigned i = (unsigned)(t - 32);
        unsigned pair = (i * 13u) % 512u;
        if (act32[2u * pair + 1u] != 0u) atomicExch(&bad_act, 1);
    }
    __syncthreads();
    if (t == 0) { g_ei_is64 = bad_ei ? 0 : 1; g_act_is64 = bad_act ? 0 : 1; }
}

// ---- init counters & colsum ----
__global__ void k_init() {
    int i = blockIdx.x * blockDim.x + threadIdx.x;
    if (i < N_NODES) g_cur[i] = 0;
    if (i < EMB)     g_colsum[i] = 0.f;
}

// ---- edge decode (vectorized, 2 edges/thread) + dst histogram ----
__global__ void k_hist(const void* __restrict__ ei) {
    int e2 = blockIdx.x * blockDim.x + threadIdx.x;
    if (e2 >= N_EDGES / 2) return;
    int s0, s1, d0, d1;
    if (g_ei_is64) {
        const longlong2* p = (const longlong2*)ei;
        longlong2 sv = p[e2];
        longlong2 dv = p[N_EDGES / 2 + e2];
        s0 = (int)sv.x; s1 = (int)sv.y;
        d0 = (int)dv.x; d1 = (int)dv.y;
    } else {
        const int2* p = (const int2*)ei;
        int2 sv = p[e2];
        int2 dv = p[N_EDGES / 2 + e2];
        s0 = sv.x; s1 = sv.y;
        d0 = dv.x; d1 = dv.y;
    }
    s0 = clampN(s0); s1 = clampN(s1);
    d0 = clampN(d0); d1 = clampN(d1);
    *(int2*)&g_src[2 * e2] = make_int2(s0, s1);
    *(int2*)&g_dst[2 * e2] = make_int2(d0, d1);
    atomicAdd(&g_cur[d0], 1);
    atomicAdd(&g_cur[d1], 1);
}

// ---- exclusive scan of counts (2-level) ----
__global__ void k_scan1() {
    __shared__ int sh[SCAN_B];
    int tid = threadIdx.x;
    int i = blockIdx.x * SCAN_B + tid;
    int c = (i < N_NODES) ? g_cur[i] : 0;
    sh[tid] = c;
    __syncthreads();
    for (int off = 1; off < SCAN_B; off <<= 1) {
        int add = (tid >= off) ? sh[tid - off] : 0;
        __syncthreads();
        sh[tid] += add;
        __syncthreads();
    }
    if (i < N_NODES) g_rowStart[i] = sh[tid] - c;
    if (tid == SCAN_B - 1) g_blockSums[blockIdx.x] = sh[tid];
}

__global__ void k_scan2() {
    int run = 0;
    for (int b = 0; b < NBLK; ++b) {
        int t = g_blockSums[b];
        g_blockSums[b] = run;
        run += t;
    }
}

__global__ void k_scan3() {
    int i = blockIdx.x * blockDim.x + threadIdx.x;
    if (i < N_NODES) {
        int v = g_rowStart[i] + g_blockSums[i >> 10];
        g_rowStart[i] = v;
        g_cur[i] = v;
    }
    if (i == 0) g_rowStart[N_NODES] = N_EDGES;
}

// ---- scatter src indices into dst-sorted order (2 edges/thread) ----
__global__ void k_scatter() {
    int e2 = blockIdx.x * blockDim.x + threadIdx.x;
    if (e2 >= N_EDGES / 2) return;
    int2 d = *(const int2*)&g_dst[2 * e2];
    int2 s = *(const int2*)&g_src[2 * e2];
    int p0 = atomicAdd(&g_cur[d.x], 1);
    int p1 = atomicAdd(&g_cur[d.y], 1);
    if (p0 >= 0 && p0 < N_EDGES) g_srcSorted[p0] = s.x;
    if (p1 >= 0 && p1 < N_EDGES) g_srcSorted[p1] = s.y;
}

// ---- embed: x = lrelu(feats @ W_embed + b), m0 = lrelu(x @ W_msg + b) ----
__global__ void __launch_bounds__(256) k_embed(
    const float* __restrict__ feats, const float* __restrict__ We,
    const float* __restrict__ be,    const float* __restrict__ Wm,
    const float* __restrict__ bm)
{
    __shared__ float sWe[NFEAT * EMB];
    __shared__ float sWm[EMB * EMB];
    __shared__ float sbe[EMB], sbm[EMB];
    __shared__ float sbuf[8 * NFEAT];
    int tid = threadIdx.x;
    for (int i = tid; i < NFEAT * EMB; i += 256) sWe[i] = We[i];
    for (int i = tid; i < EMB * EMB;   i += 256) sWm[i] = Wm[i];
    if (tid < EMB) { sbe[tid] = be[tid]; sbm[tid] = bm[tid]; }
    __syncthreads();

    int w = tid >> 5, j = tid & 31;
    int node = blockIdx.x * 8 + w;
    if (node >= N_NODES) return;

    #pragma unroll
    for (int k = 0; k < 4; ++k)
        sbuf[w * NFEAT + j + 32 * k] = feats[node * NFEAT + j + 32 * k];
    __syncwarp();

    float a = sbe[j];
    #pragma unroll 16
    for (int k = 0; k < NFEAT; ++k) a += sbuf[w * NFEAT + k] * sWe[k * EMB + j];
    float x = lrelu(a);
    g_x[node * EMB + j] = x;
    __syncwarp();
    sbuf[w * NFEAT + j] = x;
    __syncwarp();

    float mm = sbm[j];
    #pragma unroll
    for (int k = 0; k < EMB; ++k) mm += sbuf[w * NFEAT + k] * sWm[k * EMB + j];
    ((__half*)g_m0)[node * EMB + j] = __float2half(lrelu(mm));
}

// ---- one MP iteration, fused: half2 paired-edge gather, update GEMM, msg GEMM ----
__global__ void __launch_bounds__(256) k_iter(
    const float* __restrict__ Wu, const float* __restrict__ bu,
    const float* __restrict__ Wm, const float* __restrict__ bm,
    int parity, int do_colsum)
{
    __shared__ float sWu[64 * EMB];      // 8 KB
    __shared__ float sWm[EMB * EMB];     // 4 KB
    __shared__ float sbu[EMB], sbm[EMB];
    __shared__ float sbuf[8 * 64];
    __shared__ float sred[256];
    int tid = threadIdx.x;
    for (int i = tid; i < 64 * EMB;  i += 256) sWu[i] = Wu[i];
    for (int i = tid; i < EMB * EMB; i += 256) sWm[i] = Wm[i];
    if (tid < EMB) { sbu[tid] = bu[tid]; sbm[tid] = bm[tid]; }
    __syncthreads();

    const __half2* __restrict__ m_in = parity ? g_m1 : g_m0;
    __half*        __restrict__ m_out = parity ? (__half*)g_m0 : (__half*)g_m1;

    int w = tid >> 5, j = tid & 31;
    int g = j >> 4;            // half-warp: 0 -> edge e, 1 -> edge e+1
    int c = j & 15;            // half2 column pair within the 64B row
    int node = blockIdx.x * 8 + w;
    float xnew = 0.f;

    if (node < N_NODES) {
        int e   = g_rowStart[node];
        int end = g_rowStart[node + 1];
        float accx = 0.f, accy = 0.f;

        // main loop: 8 edges per step (4 pairs), half-warp per 64B m row
        for (; e + 8 <= end; e += 8) {
            int s0 = g_srcSorted[e + 0 + g];
            int s1 = g_srcSorted[e + 2 + g];
            int s2 = g_srcSorted[e + 4 + g];
            int s3 = g_srcSorted[e + 6 + g];
            float2 f0 = __half22float2(__ldcg(&m_in[s0 * 16 + c]));
            float2 f1 = __half22float2(__ldcg(&m_in[s1 * 16 + c]));
            float2 f2 = __half22float2(__ldcg(&m_in[s2 * 16 + c]));
            float2 f3 = __half22float2(__ldcg(&m_in[s3 * 16 + c]));
            accx += (f0.x + f1.x) + (f2.x + f3.x);
            accy += (f0.y + f1.y) + (f2.y + f3.y);
        }
        // tail: pairs with predication
        for (; e < end; e += 2) {
            int idx = e + g;
            if (idx < end) {
                int s = g_srcSorted[idx];
                float2 f = __half22float2(__ldcg(&m_in[s * 16 + c]));
                accx += f.x; accy += f.y;
            }
        }
        // combine the two half-warp edge groups
        accx += __shfl_xor_sync(0xffffffffu, accx, 16);
        accy += __shfl_xor_sync(0xffffffffu, accy, 16);

        float xold = g_x[node * EMB + j];
        sbuf[w * 64 + j] = xold;
        if (g == 0) {
            sbuf[w * 64 + 32 + 2 * c]     = accx;
            sbuf[w * 64 + 32 + 2 * c + 1] = accy;
        }
        __syncwarp();
        float u = sbu[j];
        #pragma unroll
        for (int k = 0; k < 64; ++k) u += sbuf[w * 64 + k] * sWu[k * EMB + j];
        xnew = lrelu(u);
        g_x[node * EMB + j] = xnew;
        __syncwarp();
        sbuf[w * 64 + j] = xnew;
        __syncwarp();
        float mm = sbm[j];
        #pragma unroll
        for (int k = 0; k < EMB; ++k) mm += sbuf[w * 64 + k] * sWm[k * EMB + j];
        m_out[node * EMB + j] = __float2half(lrelu(mm));
    }

    if (do_colsum) {     // fold global mean into the last iteration
        sred[tid] = xnew;
        __syncthreads();
        if (tid < 32) {
            float t = 0.f;
            #pragma unroll
            for (int r = 0; r < 8; ++r) t += sred[r * 32 + tid];
            atomicAdd(&g_colsum[tid], t);
        }
    }
}

// ---- head: value + softmax over 1024 actionable logits ----
__global__ void k_final(
    const void* __restrict__ act,
    const float* __restrict__ Wpol, const float* __restrict__ bpol,
    const float* __restrict__ Wval, const float* __restrict__ bval,
    float* __restrict__ out)
{
    __shared__ float sred[NACT];
    __shared__ float sWp[EMB];
    int t = threadIdx.x;
    if (t < EMB) sWp[t] = Wpol[t];
    __syncthreads();

    int node;
    if (g_act_is64) node = (int)((const long long*)act)[t];
    else            node = ((const int*)act)[t];
    node = clampN(node);

    float lg = bpol[0];
    #pragma unroll
    for (int k = 0; k < EMB; ++k) lg += g_x[node * EMB + k] * sWp[k];

    sred[t] = lg;
    __syncthreads();
    for (int off = NACT / 2; off > 0; off >>= 1) {
        if (t < off) sred[t] = fmaxf(sred[t], sred[t + off]);
        __syncthreads();
    }
    float mx = sred[0];
    __syncthreads();
    float ex = expf(lg - mx);
    sred[t] = ex;
    __syncthreads();
    for (int off = NACT / 2; off > 0; off >>= 1) {
        if (t < off) sred[t] += sred[t + off];
        __syncthreads();
    }
    float sm = sred[0];
    out[1 + t] = ex / sm;

    if (t == 0) {
        float v = bval[0];
        #pragma unroll
        for (int k = 0; k < EMB; ++k)
            v += (g_colsum[k] * (1.0f / N_NODES)) * Wval[k];
        out[0] = v;
    }
}

extern "C" void kernel_launch(void* const* d_in, const int* in_sizes, int n_in,
                              void* d_out, int out_size) {
    const float* feats = (const float*)d_in[0];
    const void*  ei    = d_in[1];
    const void*  act   = d_in[2];
    const float* We = (const float*)d_in[3];
    const float* be = (const float*)d_in[4];
    const float* Wm = (const float*)d_in[5];
    const float* bm = (const float*)d_in[6];
    const float* Wu = (const float*)d_in[7];
    const float* bu = (const float*)d_in[8];
    const float* Wv = (const float*)d_in[9];
    const float* bv = (const float*)d_in[10];
    const float* Wp = (const float*)d_in[11];
    const float* bp = (const float*)d_in[12];
    float* out = (float*)d_out;

    int nb_nodes  = (N_NODES + 255) / 256;
    int nb_edges2 = (N_EDGES / 2 + 255) / 256;
    int nb_warp8  = (N_NODES + 7) / 8;

    // dtype detection + CSR build
    k_detect <<<1, 64>>>((const unsigned*)ei, (const unsigned*)act);
    k_init   <<<nb_nodes, 256>>>();
    k_hist   <<<nb_edges2, 256>>>(ei);
    k_scan1  <<<NBLK, SCAN_B>>>();
    k_scan2  <<<1, 1>>>();
    k_scan3  <<<nb_nodes, 256>>>();
    k_scatter<<<nb_edges2, 256>>>();

    // GNN
    k_embed<<<nb_warp8, 256>>>(feats, We, be, Wm, bm);
    for (int it = 0; it < 5; ++it)
        k_iter<<<nb_warp8, 256>>>(Wu, bu, Wm, bm, it & 1, it == 4 ? 1 : 0);

    k_final<<<1, NACT>>>(act, Wp, bp, Wv, bv, out);
}